// round 2
// baseline (speedup 1.0000x reference)
#include <cuda_runtime.h>
#include <math.h>

// Problem dims
#define NB   32            // batch
#define NT   512           // seq len
#define ND   1024          // input size
#define NH   1024          // hidden size
#define NG   4096          // 4*H
#define MTOT (NB * NT)     // 16384 rows of x_proj

// Scratch (allocation-free rule: __device__ globals)
__device__ float g_xproj[(size_t)MTOT * NG];   // 256 MB
__device__ float g_c[NB * NH];                 // cell state, 128 KB

// ---------------------------------------------------------------------------
// f32x2 packed-FMA helpers (sm_103a FFMA2 — only reachable via PTX)
// ---------------------------------------------------------------------------
__device__ __forceinline__ unsigned long long pack2(float lo, float hi) {
    unsigned long long r;
    asm("mov.b64 %0, {%1, %2};" : "=l"(r) : "f"(lo), "f"(hi));
    return r;
}
__device__ __forceinline__ void ffma2(unsigned long long& d,
                                      unsigned long long a,
                                      unsigned long long b) {
    asm("fma.rn.f32x2 %0, %1, %2, %0;" : "+l"(d) : "l"(a), "l"(b));
}
__device__ __forceinline__ float2 unpack2(unsigned long long v) {
    float2 f;
    asm("mov.b64 {%0, %1}, %2;" : "=f"(f.x), "=f"(f.y) : "l"(v));
    return f;
}

__device__ __forceinline__ float sigmoidf_(float x) {
    return 1.0f / (1.0f + __expf(-x));
}
__device__ __forceinline__ float tanh_fast(float x) {
    float a = fabsf(x);
    float e = __expf(-2.0f * a);
    float r = (1.0f - e) / (1.0f + e);
    return copysignf(r, x);
}

// ---------------------------------------------------------------------------
// init: zero cell state (graph replays restart from t=0)
// ---------------------------------------------------------------------------
__global__ void init_c_kernel() {
    int i = blockIdx.x * blockDim.x + threadIdx.x;
    if (i < NB * NH) g_c[i] = 0.0f;
}

// ---------------------------------------------------------------------------
// x_proj = x @ W_ih + bias    (M=16384, N=4096, K=1024)
// 128x128x8 tiled SGEMM, 256 threads, 8x8 register tiles via FFMA2.
// ---------------------------------------------------------------------------
__global__ __launch_bounds__(256) void sgemm_xproj(const float* __restrict__ A,
                                                   const float* __restrict__ Bm,
                                                   const float* __restrict__ bias) {
    __shared__ __align__(16) float As[8 * 128];
    __shared__ __align__(16) float Bs[8 * 128];

    const int tid = threadIdx.x;
    const int rowBase = blockIdx.y * 128;
    const int colBase = blockIdx.x * 128;

    const int irA = tid >> 1;          // 0..127
    const int icA = (tid & 1) * 4;     // 0 or 4
    const int irB = tid >> 5;          // 0..7
    const int icB = (tid & 31) * 4;    // 0..124

    const int trow = tid >> 4;         // 0..15
    const int tcol = tid & 15;         // 0..15

    unsigned long long res2[8][4];
#pragma unroll
    for (int i = 0; i < 8; i++)
#pragma unroll
        for (int j = 0; j < 4; j++) res2[i][j] = 0ull;   // bits of (0.f,0.f)

    for (int bk = 0; bk < ND; bk += 8) {
        float4 a = *(const float4*)&A[(size_t)(rowBase + irA) * ND + bk + icA];
        As[(icA + 0) * 128 + irA] = a.x;
        As[(icA + 1) * 128 + irA] = a.y;
        As[(icA + 2) * 128 + irA] = a.z;
        As[(icA + 3) * 128 + irA] = a.w;
        *(float4*)&Bs[irB * 128 + icB] =
            *(const float4*)&Bm[(size_t)(bk + irB) * NG + colBase + icB];
        __syncthreads();

#pragma unroll
        for (int kk = 0; kk < 8; kk++) {
            float regM[8];
            *(float4*)&regM[0] = *(float4*)&As[kk * 128 + trow * 8];
            *(float4*)&regM[4] = *(float4*)&As[kk * 128 + trow * 8 + 4];
            ulonglong2 n01 = *(const ulonglong2*)&Bs[kk * 128 + tcol * 8];
            ulonglong2 n23 = *(const ulonglong2*)&Bs[kk * 128 + tcol * 8 + 4];
#pragma unroll
            for (int i = 0; i < 8; i++) {
                unsigned long long mm = pack2(regM[i], regM[i]);
                ffma2(res2[i][0], mm, n01.x);
                ffma2(res2[i][1], mm, n01.y);
                ffma2(res2[i][2], mm, n23.x);
                ffma2(res2[i][3], mm, n23.y);
            }
        }
        __syncthreads();
    }

#pragma unroll
    for (int i = 0; i < 8; i++) {
#pragma unroll
        for (int jp = 0; jp < 4; jp += 2) {
            int col = colBase + tcol * 8 + jp * 2;
            float2 v0 = unpack2(res2[i][jp]);
            float2 v1 = unpack2(res2[i][jp + 1]);
            float4 o;
            o.x = v0.x + bias[col + 0];
            o.y = v0.y + bias[col + 1];
            o.z = v1.x + bias[col + 2];
            o.w = v1.y + bias[col + 3];
            *(float4*)&g_xproj[(size_t)(rowBase + trow * 8 + i) * NG + col] = o;
        }
    }
}

// ---------------------------------------------------------------------------
// One LSTM timestep.
// Grid: 128 CTAs x 512 threads. CTA owns 8 h-cols (base..base+7) => 32 gate
// columns (i,f,g,o x 8). 16 warps: warp w -> K-slice ks=w>>1 (128 of K),
// col-half ch=w&1 (16 cols). lane = batch.
// Inner loop per k: 1 LDS (h, conflict-free), 4 broadcast LDS.128 (W),
// 1 pack, 8 FFMA2 -> 8x2=16 MACs/lane/k.
// K staged in 16 double-buffered chunks of 64. Partials reduced via smem,
// fused gate/c/h update. h_{t-1} read from the output tensor.
// ---------------------------------------------------------------------------
__global__ __launch_bounds__(512) void lstm_step(const float* __restrict__ Whh,
                                                 float* __restrict__ out, int t) {
    // Hs: 2 x [32][65] = 4160 floats, Ws: 2 x [64][32] = 4096 floats.
    // red: [8][32*33] = 8448 floats, aliases the whole array after final sync.
    __shared__ __align__(16) float sm[8448];
    float* Hs = sm;              // 2 x 2080
    float* Ws = sm + 4160;       // 2 x 2048

    const int tid  = threadIdx.x;
    const int base = blockIdx.x * 8;
    const int wid  = tid >> 5;       // 0..15
    const int lane = tid & 31;       // batch
    const int ks   = wid >> 1;       // 0..7  K-split
    const int ch   = wid & 1;        // col half

    unsigned long long acc[8];
#pragma unroll
    for (int j = 0; j < 8; j++) acc[j] = 0ull;

    if (t > 0) {
        const size_t hrow = (size_t)NT * NH;
        const size_t hoff = (size_t)(t - 1) * NH;

        // staging index decode (512 threads, chunk = 64 k)
        const int hl = tid & 31;         // batch row for h load
        const int hm = tid >> 5;         // float4 index 0..15 within 64-k chunk
        const int wkl = tid >> 3;        // 0..63  k within chunk for W load
        const int wc4 = tid & 7;         // col quad 0..7
        const int wg  = wc4 >> 1;        // gate
        const int wjq = (wc4 & 1) * 4;   // jj quad

        float4 hr, wr;

#define LDG_CHUNK(c)                                                            \
        {                                                                       \
            const int kb = (c) * 64;                                            \
            hr = *(const float4*)&out[(size_t)hl * hrow + hoff + kb + hm * 4];  \
            wr = *(const float4*)&Whh[(size_t)(kb + wkl) * NG + wg * 1024 +     \
                                      base + wjq];                              \
        }

#define STS_CHUNK(bf)                                                           \
        {                                                                       \
            float* hb = Hs + (bf) * 2080;                                       \
            float* wb = Ws + (bf) * 2048;                                       \
            hb[hl * 65 + hm * 4 + 0] = hr.x;                                    \
            hb[hl * 65 + hm * 4 + 1] = hr.y;                                    \
            hb[hl * 65 + hm * 4 + 2] = hr.z;                                    \
            hb[hl * 65 + hm * 4 + 3] = hr.w;                                    \
            *(float4*)&wb[wkl * 32 + wc4 * 4] = wr;                             \
        }

        LDG_CHUNK(0);
        STS_CHUNK(0);
        __syncthreads();

        for (int c = 0; c < 16; c++) {
            if (c < 15) LDG_CHUNK(c + 1);

            const int bf = c & 1;
            const float* hb = Hs + bf * 2080 + lane * 65 + ks * 8;
            const float* wb = Ws + bf * 2048 + ch * 16 + ks * 8 * 32;

#pragma unroll
            for (int kk = 0; kk < 8; kk++) {
                float h = hb[kk];
                unsigned long long hh = pack2(h, h);
                const float* wrow = wb + kk * 32;
                ulonglong2 wA = *(const ulonglong2*)(wrow);
                ulonglong2 wB = *(const ulonglong2*)(wrow + 4);
                ulonglong2 wC = *(const ulonglong2*)(wrow + 8);
                ulonglong2 wD = *(const ulonglong2*)(wrow + 12);
                ffma2(acc[0], hh, wA.x);
                ffma2(acc[1], hh, wA.y);
                ffma2(acc[2], hh, wB.x);
                ffma2(acc[3], hh, wB.y);
                ffma2(acc[4], hh, wC.x);
                ffma2(acc[5], hh, wC.y);
                ffma2(acc[6], hh, wD.x);
                ffma2(acc[7], hh, wD.y);
            }

            if (c < 15) STS_CHUNK((c + 1) & 1);
            __syncthreads();
        }
#undef LDG_CHUNK
#undef STS_CHUNK
    }

    // write K-split partials (red aliases Hs/Ws; all compute synced above)
    float* red = sm;   // [8][32*33]
    {
        float* r = red + ks * 1056 + lane * 33 + ch * 16;
#pragma unroll
        for (int j = 0; j < 8; j++) {
            float2 v = unpack2(acc[j]);
            r[2 * j + 0] = v.x;
            r[2 * j + 1] = v.y;
        }
    }
    __syncthreads();

    // fused gate nonlinearity + c/h update; thread owns (b, jj)
    if (tid < 256) {
        const int b  = tid >> 3;     // 0..31
        const int jj = tid & 7;      // 0..7
        float gate[4];
#pragma unroll
        for (int g = 0; g < 4; g++) {
            const int col = g * 8 + jj;
            float s = 0.0f;
#pragma unroll
            for (int kv = 0; kv < 8; kv++) s += red[kv * 1056 + b * 33 + col];
            s += g_xproj[((size_t)b * NT + t) * NG + g * 1024 + base + jj];
            gate[g] = s;
        }
        const float ig = sigmoidf_(gate[0]);
        const float fg = sigmoidf_(gate[1]);
        const float gg = tanh_fast(gate[2]);
        const float og = sigmoidf_(gate[3]);

        const int ci = b * NH + base + jj;
        const float c = fg * g_c[ci] + ig * gg;
        g_c[ci] = c;
        out[((size_t)b * NT + t) * NH + base + jj] = og * tanh_fast(c);
    }
}

// ---------------------------------------------------------------------------
// finalize: append h_T and c_T after hidden_seq (flattened pytree order:
// hidden_seq, h_T, c_T)
// ---------------------------------------------------------------------------
__global__ void finalize_kernel(float* __restrict__ out) {
    int i = blockIdx.x * blockDim.x + threadIdx.x;
    if (i < NB * NH) {
        const size_t HS = (size_t)NB * NT * NH;
        int b = i >> 10;
        int k = i & 1023;
        out[HS + i] = out[((size_t)b * NT + (NT - 1)) * NH + k];
        out[HS + NB * NH + i] = g_c[i];
    }
}

// ---------------------------------------------------------------------------
// launch
// ---------------------------------------------------------------------------
extern "C" void kernel_launch(void* const* d_in, const int* in_sizes, int n_in,
                              void* d_out, int out_size) {
    const float* x    = (const float*)d_in[0];
    const float* wih  = (const float*)d_in[1];
    const float* whh  = (const float*)d_in[2];
    const float* bias = (const float*)d_in[3];
    float* out = (float*)d_out;

    (void)in_sizes; (void)n_in;

    init_c_kernel<<<(NB * NH + 255) / 256, 256>>>();

    {
        dim3 grid(NG / 128, MTOT / 128);   // (32, 128)
        sgemm_xproj<<<grid, 256>>>(x, wih, bias);
    }

    for (int t = 0; t < NT; t++) {
        lstm_step<<<NH / 8, 512>>>(whh, out, t);
    }

    if (out_size >= NB * NT * NH + 2 * NB * NH) {
        finalize_kernel<<<(NB * NH + 255) / 256, 256>>>(out);
    }
}